// round 2
// baseline (speedup 1.0000x reference)
#include <cuda_runtime.h>
#include <cuda_bf16.h>
#include <math.h>

// Problem dims (fixed)
#define Bq  4
#define Tq  2048
#define Cq  1024
#define Hq  16
#define HDq 64
#define BT  8192   // B*T
#define BHq 64     // B*H

// Scratch (device globals — no allocation allowed)
__device__ float g_qkv[BT * 3 * Cq];       // [8192, 3072]
__device__ float g_q[BHq * Tq * HDq];      // [b*H+h, t, d]
__device__ float g_k[BHq * Tq * HDq];
__device__ float g_v[BHq * Tq * HDq];
__device__ float g_o[BT * Cq];             // [8192, 1024] attn output (b,t,h,d)

// ---------------------------------------------------------------------------
// SGEMM: C[M,N] = A[M,K] @ B[N,K]^T   (both row-major, K contiguous)
// 128x128 tile, BK=8, 256 threads, 8x8 per-thread
// ---------------------------------------------------------------------------
__global__ __launch_bounds__(256) void sgemm_nt(
    const float* __restrict__ A, const float* __restrict__ B,
    float* __restrict__ C, int M, int N, int K)
{
    const int BK = 8;
    __shared__ float As[BK][128];
    __shared__ float Bs[BK][128];

    int tid = threadIdx.x;
    int tx = tid & 15;          // 0..15  -> N dim
    int ty = tid >> 4;          // 0..15  -> M dim
    int lr = tid >> 1;          // 0..127 load row
    int lc = (tid & 1) * 4;     // 0 or 4 load col (float4)

    const float* Ap = A + (size_t)(blockIdx.y * 128 + lr) * K + lc;
    const float* Bp = B + (size_t)(blockIdx.x * 128 + lr) * K + lc;

    float acc[8][8];
#pragma unroll
    for (int i = 0; i < 8; i++)
#pragma unroll
        for (int j = 0; j < 8; j++) acc[i][j] = 0.f;

    for (int k0 = 0; k0 < K; k0 += BK) {
        float4 a4 = *(const float4*)(Ap + k0);
        float4 b4 = *(const float4*)(Bp + k0);
        As[lc + 0][lr] = a4.x; As[lc + 1][lr] = a4.y;
        As[lc + 2][lr] = a4.z; As[lc + 3][lr] = a4.w;
        Bs[lc + 0][lr] = b4.x; Bs[lc + 1][lr] = b4.y;
        Bs[lc + 2][lr] = b4.z; Bs[lc + 3][lr] = b4.w;
        __syncthreads();
#pragma unroll
        for (int k = 0; k < BK; k++) {
            float4 ra0 = *(const float4*)&As[k][ty * 8];
            float4 ra1 = *(const float4*)&As[k][ty * 8 + 4];
            float4 rb0 = *(const float4*)&Bs[k][tx * 8];
            float4 rb1 = *(const float4*)&Bs[k][tx * 8 + 4];
            float ra[8] = {ra0.x, ra0.y, ra0.z, ra0.w, ra1.x, ra1.y, ra1.z, ra1.w};
            float rb[8] = {rb0.x, rb0.y, rb0.z, rb0.w, rb1.x, rb1.y, rb1.z, rb1.w};
#pragma unroll
            for (int i = 0; i < 8; i++)
#pragma unroll
                for (int j = 0; j < 8; j++) acc[i][j] += ra[i] * rb[j];
        }
        __syncthreads();
    }

    float* Cp = C + (size_t)(blockIdx.y * 128 + ty * 8) * N + blockIdx.x * 128 + tx * 8;
#pragma unroll
    for (int i = 0; i < 8; i++) {
        float4 w0 = {acc[i][0], acc[i][1], acc[i][2], acc[i][3]};
        float4 w1 = {acc[i][4], acc[i][5], acc[i][6], acc[i][7]};
        *(float4*)(Cp + (size_t)i * N) = w0;
        *(float4*)(Cp + (size_t)i * N + 4) = w1;
    }
}

// ---------------------------------------------------------------------------
// RMSNorm + RoPE + layout transform.  One warp per (b, t, h).
// qkv: [8192, 3072]; outputs [b*H+h, t, 64]
// ---------------------------------------------------------------------------
__device__ __forceinline__ float warp_sum(float v) {
    v += __shfl_xor_sync(0xffffffffu, v, 16);
    v += __shfl_xor_sync(0xffffffffu, v, 8);
    v += __shfl_xor_sync(0xffffffffu, v, 4);
    v += __shfl_xor_sync(0xffffffffu, v, 2);
    v += __shfl_xor_sync(0xffffffffu, v, 1);
    return v;
}

__global__ __launch_bounds__(256) void norm_rope(
    const float* __restrict__ qkv,
    float* __restrict__ gq, float* __restrict__ gk, float* __restrict__ gv)
{
    int gw = (blockIdx.x * 256 + threadIdx.x) >> 5;   // global warp id
    int lane = threadIdx.x & 31;
    // gw = (b*T + t)*H + h
    int h = gw & (Hq - 1);
    int t = (gw >> 4) & (Tq - 1);
    int b = gw >> 15;

    const float* base = qkv + (size_t)(b * Tq + t) * (3 * Cq) + h * HDq;
    float q1 = base[lane],          q2 = base[lane + 32];
    float k1 = base[Cq + lane],     k2 = base[Cq + lane + 32];
    float v1 = base[2 * Cq + lane], v2 = base[2 * Cq + lane + 32];

    float sq = warp_sum(q1 * q1 + q2 * q2);
    float sk = warp_sum(k1 * k1 + k2 * k2);
    const float eps = 1.1920929e-7f;  // finfo(float32).eps
    float rq = rsqrtf(sq * (1.f / 64.f) + eps);
    float rk = rsqrtf(sk * (1.f / 64.f) + eps);
    q1 *= rq; q2 *= rq; k1 *= rk; k2 *= rk;

    // rotary: i = lane (half = 32); cos/sin rounded through bf16 like reference
    float inv = powf(10000.f, -(float)lane * (1.f / 32.f));
    float fr = (float)t * inv;
    float c = __bfloat162float(__float2bfloat16(cosf(fr)));
    float s = __bfloat162float(__float2bfloat16(sinf(fr)));

    size_t o = ((size_t)(b * Hq + h) * Tq + t) * HDq;
    gq[o + lane]      =  q1 * c + q2 * s;
    gq[o + lane + 32] = -q1 * s + q2 * c;
    gk[o + lane]      =  k1 * c + k2 * s;
    gk[o + lane + 32] = -k1 * s + k2 * c;
    gv[o + lane]      = v1;
    gv[o + lane + 32] = v2;
}

// ---------------------------------------------------------------------------
// Flash attention (fp32), 64x64 tiles, 256 threads, online softmax.
// grid: (T/64, B*H).  Q/K stored d-major with stride 65 (conflict-free-ish).
// Output written as [b, t, h*64+d] = [8192, 1024].
// ---------------------------------------------------------------------------
#define QS_STRIDE 65
#define ATTN_SMEM_FLOATS (2 * 64 * QS_STRIDE + 64 * 64 + 64 * 64 + 3 * 64)
#define ATTN_SMEM_BYTES  (ATTN_SMEM_FLOATS * 4)

__global__ __launch_bounds__(256) void attn_kernel(
    const float* __restrict__ gq, const float* __restrict__ gk,
    const float* __restrict__ gv, float* __restrict__ go)
{
    extern __shared__ float sm[];
    float* Qs = sm;                         // [64 d][65]
    float* Ks = Qs + 64 * QS_STRIDE;        // [64 d][65]
    float* Vs = Ks + 64 * QS_STRIDE;        // [64 kv][64 d]
    float* Ss = Vs + 64 * 64;               // [64 q][64 kv]
    float* Ms = Ss + 64 * 64;               // [64]
    float* Ls = Ms + 64;                    // [64]
    float* Cs = Ls + 64;                    // [64]

    int tid = threadIdx.x;
    int tx = tid & 15;        // kv / hd column group
    int ty = tid >> 4;        // q row group

    int qb = blockIdx.x;
    int bh = blockIdx.y;
    const float* qbase = gq + ((size_t)bh * Tq + qb * 64) * 64;
    const float* kbase = gk + (size_t)bh * Tq * 64;
    const float* vbase = gv + (size_t)bh * Tq * 64;

    // Load Q transposed (d-major)
    for (int i = tid; i < 1024; i += 256) {
        int r = i >> 4, c = (i & 15) << 2;
        float4 q4 = *(const float4*)(qbase + r * 64 + c);
        Qs[(c + 0) * QS_STRIDE + r] = q4.x;
        Qs[(c + 1) * QS_STRIDE + r] = q4.y;
        Qs[(c + 2) * QS_STRIDE + r] = q4.z;
        Qs[(c + 3) * QS_STRIDE + r] = q4.w;
    }
    if (tid < 64) { Ms[tid] = -INFINITY; Ls[tid] = 0.f; }

    float o[4][4];
#pragma unroll
    for (int i = 0; i < 4; i++)
#pragma unroll
        for (int j = 0; j < 4; j++) o[i][j] = 0.f;

    const float scale = 0.125f;   // 1/sqrt(64)
    int q0 = qb * 64 + ty * 4;

    for (int kb = 0; kb <= qb; kb++) {
        __syncthreads();   // previous PV done reading Ks/Vs/Ss
        for (int i = tid; i < 1024; i += 256) {
            int r = i >> 4, c = (i & 15) << 2;
            float4 k4 = *(const float4*)(kbase + (size_t)(kb * 64 + r) * 64 + c);
            Ks[(c + 0) * QS_STRIDE + r] = k4.x;
            Ks[(c + 1) * QS_STRIDE + r] = k4.y;
            Ks[(c + 2) * QS_STRIDE + r] = k4.z;
            Ks[(c + 3) * QS_STRIDE + r] = k4.w;
            float4 v4 = *(const float4*)(vbase + (size_t)(kb * 64 + r) * 64 + c);
            *(float4*)&Vs[r * 64 + c] = v4;
        }
        __syncthreads();

        // S = Q @ K^T  (4x4 per thread, inner over d)
        float s[4][4];
#pragma unroll
        for (int i = 0; i < 4; i++)
#pragma unroll
            for (int j = 0; j < 4; j++) s[i][j] = 0.f;
#pragma unroll 8
        for (int d = 0; d < 64; d++) {
            float a0 = Qs[d * QS_STRIDE + ty * 4 + 0];
            float a1 = Qs[d * QS_STRIDE + ty * 4 + 1];
            float a2 = Qs[d * QS_STRIDE + ty * 4 + 2];
            float a3 = Qs[d * QS_STRIDE + ty * 4 + 3];
            float b0 = Ks[d * QS_STRIDE + tx * 4 + 0];
            float b1 = Ks[d * QS_STRIDE + tx * 4 + 1];
            float b2 = Ks[d * QS_STRIDE + tx * 4 + 2];
            float b3 = Ks[d * QS_STRIDE + tx * 4 + 3];
            s[0][0] += a0 * b0; s[0][1] += a0 * b1; s[0][2] += a0 * b2; s[0][3] += a0 * b3;
            s[1][0] += a1 * b0; s[1][1] += a1 * b1; s[1][2] += a1 * b2; s[1][3] += a1 * b3;
            s[2][0] += a2 * b0; s[2][1] += a2 * b1; s[2][2] += a2 * b2; s[2][3] += a2 * b3;
            s[3][0] += a3 * b0; s[3][1] += a3 * b1; s[3][2] += a3 * b2; s[3][3] += a3 * b3;
        }

        int kc = kb * 64 + tx * 4;
        if (kb == qb) {
#pragma unroll
            for (int i = 0; i < 4; i++) {
                int qi = q0 + i;
                float4 w;
                w.x = (kc + 0 <= qi) ? s[i][0] * scale : -INFINITY;
                w.y = (kc + 1 <= qi) ? s[i][1] * scale : -INFINITY;
                w.z = (kc + 2 <= qi) ? s[i][2] * scale : -INFINITY;
                w.w = (kc + 3 <= qi) ? s[i][3] * scale : -INFINITY;
                *(float4*)&Ss[(ty * 4 + i) * 64 + tx * 4] = w;
            }
        } else {
#pragma unroll
            for (int i = 0; i < 4; i++) {
                float4 w = {s[i][0] * scale, s[i][1] * scale, s[i][2] * scale, s[i][3] * scale};
                *(float4*)&Ss[(ty * 4 + i) * 64 + tx * 4] = w;
            }
        }
        __syncthreads();

        // Online softmax: 4 threads per row, 16 elems each
        {
            int row = tid >> 2, part = tid & 3;
            float* sr = Ss + row * 64 + part * 16;
            float mloc = sr[0];
#pragma unroll
            for (int e = 1; e < 16; e++) mloc = fmaxf(mloc, sr[e]);
            mloc = fmaxf(mloc, __shfl_xor_sync(0xffffffffu, mloc, 1));
            mloc = fmaxf(mloc, __shfl_xor_sync(0xffffffffu, mloc, 2));
            float mold = Ms[row];
            float mnew = fmaxf(mold, mloc);
            float suml = 0.f;
#pragma unroll
            for (int e = 0; e < 16; e++) {
                float p = __expf(sr[e] - mnew);
                sr[e] = p;
                suml += p;
            }
            suml += __shfl_xor_sync(0xffffffffu, suml, 1);
            suml += __shfl_xor_sync(0xffffffffu, suml, 2);
            if (part == 0) {
                float corr = __expf(mold - mnew);   // 0 on first tile (mold=-inf)
                Cs[row] = corr;
                Ls[row] = Ls[row] * corr + suml;
                Ms[row] = mnew;
            }
        }
        __syncthreads();

        // Rescale O, accumulate P @ V
        float c0 = Cs[ty * 4 + 0], c1 = Cs[ty * 4 + 1];
        float c2 = Cs[ty * 4 + 2], c3 = Cs[ty * 4 + 3];
#pragma unroll
        for (int j = 0; j < 4; j++) {
            o[0][j] *= c0; o[1][j] *= c1; o[2][j] *= c2; o[3][j] *= c3;
        }
#pragma unroll 8
        for (int kk = 0; kk < 64; kk++) {
            float p0 = Ss[(ty * 4 + 0) * 64 + kk];
            float p1 = Ss[(ty * 4 + 1) * 64 + kk];
            float p2 = Ss[(ty * 4 + 2) * 64 + kk];
            float p3 = Ss[(ty * 4 + 3) * 64 + kk];
            float4 v4 = *(const float4*)&Vs[kk * 64 + tx * 4];
            o[0][0] += p0 * v4.x; o[0][1] += p0 * v4.y; o[0][2] += p0 * v4.z; o[0][3] += p0 * v4.w;
            o[1][0] += p1 * v4.x; o[1][1] += p1 * v4.y; o[1][2] += p1 * v4.z; o[1][3] += p1 * v4.w;
            o[2][0] += p2 * v4.x; o[2][1] += p2 * v4.y; o[2][2] += p2 * v4.z; o[2][3] += p2 * v4.w;
            o[3][0] += p3 * v4.x; o[3][1] += p3 * v4.y; o[3][2] += p3 * v4.z; o[3][3] += p3 * v4.w;
        }
    }

    // Epilogue: normalize and write [b, t, h*64+d]
    int b = bh >> 4, h = bh & 15;
#pragma unroll
    for (int i = 0; i < 4; i++) {
        float invl = 1.f / Ls[ty * 4 + i];
        int qg = qb * 64 + ty * 4 + i;
        float4 w = {o[i][0] * invl, o[i][1] * invl, o[i][2] * invl, o[i][3] * invl};
        *(float4*)(go + (size_t)(b * Tq + qg) * Cq + h * 64 + tx * 4) = w;
    }
}

// ---------------------------------------------------------------------------
extern "C" void kernel_launch(void* const* d_in, const int* in_sizes, int n_in,
                              void* d_out, int out_size)
{
    const float* x      = (const float*)d_in[0];   // [4,2048,1024]
    const float* w_attn = (const float*)d_in[1];   // [3072,1024]
    const float* w_proj = (const float*)d_in[2];   // [1024,1024]
    float* out = (float*)d_out;                    // [4,2048,1024]

    float *qkv, *q, *k, *v, *o;
    cudaGetSymbolAddress((void**)&qkv, g_qkv);
    cudaGetSymbolAddress((void**)&q,   g_q);
    cudaGetSymbolAddress((void**)&k,   g_k);
    cudaGetSymbolAddress((void**)&v,   g_v);
    cudaGetSymbolAddress((void**)&o,   g_o);

    // 1) qkv = x @ w_attn^T   [8192,3072]
    sgemm_nt<<<dim3(3072 / 128, BT / 128), 256>>>(x, w_attn, qkv, BT, 3 * Cq, Cq);

    // 2) RMSNorm + RoPE + relayout
    norm_rope<<<(Bq * Tq * Hq) / 8, 256>>>(qkv, q, k, v);

    // 3) causal flash attention
    cudaFuncSetAttribute(attn_kernel, cudaFuncAttributeMaxDynamicSharedMemorySize,
                         ATTN_SMEM_BYTES);
    attn_kernel<<<dim3(Tq / 64, BHq), 256, ATTN_SMEM_BYTES>>>(q, k, v, o);

    // 4) out = o @ w_proj^T   [8192,1024]
    sgemm_nt<<<dim3(Cq / 128, BT / 128), 256>>>(o, w_proj, out, BT, Cq, Cq);
}

// round 4
// speedup vs baseline: 1.3499x; 1.3499x over previous
#include <cuda_runtime.h>
#include <cuda_bf16.h>
#include <math.h>
#include <stdint.h>

// Problem dims (fixed)
#define Bq  4
#define Tq  2048
#define Cq  1024
#define Hq  16
#define HDq 64
#define BT  8192   // B*T
#define BHq 64     // B*H

// Scratch (device globals — no allocation allowed)
__device__ float g_qkv[BT * 3 * Cq];       // [8192, 3072]
__device__ float g_q[BHq * Tq * HDq];      // [b*H+h, t, d]
__device__ float g_k[BHq * Tq * HDq];
__device__ float g_v[BHq * Tq * HDq];
__device__ float g_o[BT * Cq];             // [8192, 1024] attn output (b,t,h,d)

// ---------------------------------------------------------------------------
// SGEMM: C[M,N] = A[M,K] @ B[N,K]^T   (both row-major, K contiguous)
// 128x128 tile, BK=8, 256 threads, 8x8 per-thread   (unchanged from R0)
// ---------------------------------------------------------------------------
__global__ __launch_bounds__(256) void sgemm_nt(
    const float* __restrict__ A, const float* __restrict__ B,
    float* __restrict__ C, int M, int N, int K)
{
    const int BK = 8;
    __shared__ float As[BK][128];
    __shared__ float Bs[BK][128];

    int tid = threadIdx.x;
    int tx = tid & 15;
    int ty = tid >> 4;
    int lr = tid >> 1;
    int lc = (tid & 1) * 4;

    const float* Ap = A + (size_t)(blockIdx.y * 128 + lr) * K + lc;
    const float* Bp = B + (size_t)(blockIdx.x * 128 + lr) * K + lc;

    float acc[8][8];
#pragma unroll
    for (int i = 0; i < 8; i++)
#pragma unroll
        for (int j = 0; j < 8; j++) acc[i][j] = 0.f;

    for (int k0 = 0; k0 < K; k0 += BK) {
        float4 a4 = *(const float4*)(Ap + k0);
        float4 b4 = *(const float4*)(Bp + k0);
        As[lc + 0][lr] = a4.x; As[lc + 1][lr] = a4.y;
        As[lc + 2][lr] = a4.z; As[lc + 3][lr] = a4.w;
        Bs[lc + 0][lr] = b4.x; Bs[lc + 1][lr] = b4.y;
        Bs[lc + 2][lr] = b4.z; Bs[lc + 3][lr] = b4.w;
        __syncthreads();
#pragma unroll
        for (int k = 0; k < BK; k++) {
            float4 ra0 = *(const float4*)&As[k][ty * 8];
            float4 ra1 = *(const float4*)&As[k][ty * 8 + 4];
            float4 rb0 = *(const float4*)&Bs[k][tx * 8];
            float4 rb1 = *(const float4*)&Bs[k][tx * 8 + 4];
            float ra[8] = {ra0.x, ra0.y, ra0.z, ra0.w, ra1.x, ra1.y, ra1.z, ra1.w};
            float rb[8] = {rb0.x, rb0.y, rb0.z, rb0.w, rb1.x, rb1.y, rb1.z, rb1.w};
#pragma unroll
            for (int i = 0; i < 8; i++)
#pragma unroll
                for (int j = 0; j < 8; j++) acc[i][j] += ra[i] * rb[j];
        }
        __syncthreads();
    }

    float* Cp = C + (size_t)(blockIdx.y * 128 + ty * 8) * N + blockIdx.x * 128 + tx * 8;
#pragma unroll
    for (int i = 0; i < 8; i++) {
        float4 w0 = {acc[i][0], acc[i][1], acc[i][2], acc[i][3]};
        float4 w1 = {acc[i][4], acc[i][5], acc[i][6], acc[i][7]};
        *(float4*)(Cp + (size_t)i * N) = w0;
        *(float4*)(Cp + (size_t)i * N + 4) = w1;
    }
}

// ---------------------------------------------------------------------------
// RMSNorm + RoPE + layout transform.  One warp per (b, t, h).  (unchanged)
// ---------------------------------------------------------------------------
__device__ __forceinline__ float warp_sum(float v) {
    v += __shfl_xor_sync(0xffffffffu, v, 16);
    v += __shfl_xor_sync(0xffffffffu, v, 8);
    v += __shfl_xor_sync(0xffffffffu, v, 4);
    v += __shfl_xor_sync(0xffffffffu, v, 2);
    v += __shfl_xor_sync(0xffffffffu, v, 1);
    return v;
}

__global__ __launch_bounds__(256) void norm_rope(
    const float* __restrict__ qkv,
    float* __restrict__ gq, float* __restrict__ gk, float* __restrict__ gv)
{
    int gw = (blockIdx.x * 256 + threadIdx.x) >> 5;
    int lane = threadIdx.x & 31;
    int h = gw & (Hq - 1);
    int t = (gw >> 4) & (Tq - 1);
    int b = gw >> 15;

    const float* base = qkv + (size_t)(b * Tq + t) * (3 * Cq) + h * HDq;
    float q1 = base[lane],          q2 = base[lane + 32];
    float k1 = base[Cq + lane],     k2 = base[Cq + lane + 32];
    float v1 = base[2 * Cq + lane], v2 = base[2 * Cq + lane + 32];

    float sq = warp_sum(q1 * q1 + q2 * q2);
    float sk = warp_sum(k1 * k1 + k2 * k2);
    const float eps = 1.1920929e-7f;
    float rq = rsqrtf(sq * (1.f / 64.f) + eps);
    float rk = rsqrtf(sk * (1.f / 64.f) + eps);
    q1 *= rq; q2 *= rq; k1 *= rk; k2 *= rk;

    float inv = powf(10000.f, -(float)lane * (1.f / 32.f));
    float fr = (float)t * inv;
    float c = __bfloat162float(__float2bfloat16(cosf(fr)));
    float s = __bfloat162float(__float2bfloat16(sinf(fr)));

    size_t o = ((size_t)(b * Hq + h) * Tq + t) * HDq;
    gq[o + lane]      =  q1 * c + q2 * s;
    gq[o + lane + 32] = -q1 * s + q2 * c;
    gk[o + lane]      =  k1 * c + k2 * s;
    gk[o + lane + 32] = -k1 * s + k2 * c;
    gv[o + lane]      = v1;
    gv[o + lane + 32] = v2;
}

// ---------------------------------------------------------------------------
// Flash attention with tf32 mma.sync (m16n8k8), fp32 accumulate.
// CTA tile: 128 q rows x 64 kv.  256 threads = 8 warps, warp = 16 q rows.
// grid: (T/128, B*H).  Output written as [b, t, h*64+d].
// ---------------------------------------------------------------------------
#define QSTR 68   // Qs/Ks/Ss stride (bank = lane for frag loads)
#define VSTR 72   // Vs stride (bank = tg*8+gr, full permutation)
#define ATTN_SMEM_FLOATS (128*QSTR + 64*QSTR + 64*VSTR + 128*QSTR + 3*128)
#define ATTN_SMEM_BYTES  (ATTN_SMEM_FLOATS * 4)

__device__ __forceinline__ uint32_t f2tf(float f) {
    uint32_t r;
    asm("cvt.rna.tf32.f32 %0, %1;" : "=r"(r) : "f"(f));
    return r;
}
__device__ __forceinline__ uint4 tf4(float4 v) {
    uint4 u;
    u.x = f2tf(v.x); u.y = f2tf(v.y); u.z = f2tf(v.z); u.w = f2tf(v.w);
    return u;
}
__device__ __forceinline__ void mma_tf32(float c[4],
    uint32_t a0, uint32_t a1, uint32_t a2, uint32_t a3,
    uint32_t b0, uint32_t b1)
{
    asm volatile(
        "mma.sync.aligned.m16n8k8.row.col.f32.tf32.tf32.f32 "
        "{%0,%1,%2,%3}, {%4,%5,%6,%7}, {%8,%9}, {%0,%1,%2,%3};"
        : "+f"(c[0]), "+f"(c[1]), "+f"(c[2]), "+f"(c[3])
        : "r"(a0), "r"(a1), "r"(a2), "r"(a3), "r"(b0), "r"(b1));
}

__global__ __launch_bounds__(256) void attn_kernel(
    const float* __restrict__ gq, const float* __restrict__ gk,
    const float* __restrict__ gv, float* __restrict__ go)
{
    extern __shared__ float sm[];
    float* Qs = sm;                       // [128][QSTR] tf32 bits
    float* Ks = Qs + 128 * QSTR;          // [64][QSTR]
    float* Vs = Ks + 64 * QSTR;           // [64][VSTR]
    float* Ss = Vs + 64 * VSTR;           // [128][QSTR]  scores -> P
    float* Ms = Ss + 128 * QSTR;          // [128]
    float* Ls = Ms + 128;                 // [128]
    float* Cs = Ls + 128;                 // [128]

    int tid = threadIdx.x;
    int wid = tid >> 5;
    int lane = tid & 31;
    int gr = lane >> 2;       // group id (0..7)
    int tg = lane & 3;        // thread in group
    int q0w = wid * 16;       // warp's first q row within tile

    int qb = (gridDim.x - 1) - blockIdx.x;   // reversed: big-work CTAs first
    int bh = blockIdx.y;
    const float* qbase = gq + ((size_t)bh * Tq + qb * 128) * 64;
    const float* kbase = gk + (size_t)bh * Tq * 64;
    const float* vbase = gv + (size_t)bh * Tq * 64;

    // Load Q tile (tf32-converted), init M/L
    for (int i = tid; i < 2048; i += 256) {
        int r = i >> 4, c = (i & 15) << 2;
        float4 q4 = *(const float4*)(qbase + (size_t)r * 64 + c);
        *(uint4*)&Qs[r * QSTR + c] = tf4(q4);
    }
    if (tid < 128) { Ms[tid] = -INFINITY; Ls[tid] = 0.f; }

    float of[8][4];
#pragma unroll
    for (int nt = 0; nt < 8; nt++)
#pragma unroll
        for (int j = 0; j < 4; j++) of[nt][j] = 0.f;

    const float scale = 0.125f;
    int nkb = 2 * qb + 2;

    for (int kb = 0; kb < nkb; kb++) {
        __syncthreads();   // prev PV done with Ks/Vs/Ss; covers Qs/Ms/Ls on first iter
        for (int i = tid; i < 1024; i += 256) {
            int r = i >> 4, c = (i & 15) << 2;
            float4 k4 = *(const float4*)(kbase + (size_t)(kb * 64 + r) * 64 + c);
            *(uint4*)&Ks[r * QSTR + c] = tf4(k4);
            float4 v4 = *(const float4*)(vbase + (size_t)(kb * 64 + r) * 64 + c);
            *(uint4*)&Vs[r * VSTR + c] = tf4(v4);
        }
        __syncthreads();

        // ---- S = Q @ K^T via tf32 mma ----
        float sc[8][4];
#pragma unroll
        for (int nt = 0; nt < 8; nt++)
#pragma unroll
            for (int j = 0; j < 4; j++) sc[nt][j] = 0.f;

#pragma unroll
        for (int kc = 0; kc < 8; kc++) {
            uint32_t a0 = __float_as_uint(Qs[(q0w + gr)     * QSTR + kc * 8 + tg]);
            uint32_t a1 = __float_as_uint(Qs[(q0w + gr + 8) * QSTR + kc * 8 + tg]);
            uint32_t a2 = __float_as_uint(Qs[(q0w + gr)     * QSTR + kc * 8 + tg + 4]);
            uint32_t a3 = __float_as_uint(Qs[(q0w + gr + 8) * QSTR + kc * 8 + tg + 4]);
#pragma unroll
            for (int nt = 0; nt < 8; nt++) {
                uint32_t b0 = __float_as_uint(Ks[(nt * 8 + gr) * QSTR + kc * 8 + tg]);
                uint32_t b1 = __float_as_uint(Ks[(nt * 8 + gr) * QSTR + kc * 8 + tg + 4]);
                mma_tf32(sc[nt], a0, a1, a2, a3, b0, b1);
            }
        }

        // scale + causal mask + store to Ss
        {
            int r0 = q0w + gr;
            bool diag = (kb >= 2 * qb);
            int qg0 = qb * 128 + r0;
            int qg1 = qg0 + 8;
#pragma unroll
            for (int nt = 0; nt < 8; nt++) {
                int col = nt * 8 + 2 * tg;
                float2 lo = {sc[nt][0] * scale, sc[nt][1] * scale};
                float2 hi = {sc[nt][2] * scale, sc[nt][3] * scale};
                if (diag) {
                    int kvg = kb * 64 + col;
                    if (kvg     > qg0) lo.x = -INFINITY;
                    if (kvg + 1 > qg0) lo.y = -INFINITY;
                    if (kvg     > qg1) hi.x = -INFINITY;
                    if (kvg + 1 > qg1) hi.y = -INFINITY;
                }
                *(float2*)&Ss[r0 * QSTR + col]       = lo;
                *(float2*)&Ss[(r0 + 8) * QSTR + col] = hi;
            }
        }
        __syncthreads();

        // ---- online softmax (2 threads per row, 32 elems each) ----
        {
            int row = tid >> 1, part = tid & 1;
            float* sr = Ss + row * QSTR + part * 32;
            float mloc = sr[0];
#pragma unroll
            for (int e = 1; e < 32; e++) mloc = fmaxf(mloc, sr[e]);
            mloc = fmaxf(mloc, __shfl_xor_sync(0xffffffffu, mloc, 1));
            float mold = Ms[row];
            float mnew = fmaxf(mold, mloc);
            float suml = 0.f;
#pragma unroll
            for (int e = 0; e < 32; e++) {
                float p = __expf(sr[e] - mnew);
                sr[e] = p;
                suml += p;
            }
            suml += __shfl_xor_sync(0xffffffffu, suml, 1);
            if (part == 0) {
                float corr = __expf(mold - mnew);
                Cs[row] = corr;
                Ls[row] = Ls[row] * corr + suml;
                Ms[row] = mnew;
            }
        }
        __syncthreads();

        // ---- O = O*corr + P @ V via tf32 mma ----
        float c_lo = Cs[q0w + gr], c_hi = Cs[q0w + gr + 8];
#pragma unroll
        for (int nt = 0; nt < 8; nt++) {
            of[nt][0] *= c_lo; of[nt][1] *= c_lo;
            of[nt][2] *= c_hi; of[nt][3] *= c_hi;
        }
#pragma unroll
        for (int kc = 0; kc < 8; kc++) {
            uint32_t a0 = f2tf(Ss[(q0w + gr)     * QSTR + kc * 8 + tg]);
            uint32_t a1 = f2tf(Ss[(q0w + gr + 8) * QSTR + kc * 8 + tg]);
            uint32_t a2 = f2tf(Ss[(q0w + gr)     * QSTR + kc * 8 + tg + 4]);
            uint32_t a3 = f2tf(Ss[(q0w + gr + 8) * QSTR + kc * 8 + tg + 4]);
#pragma unroll
            for (int nt = 0; nt < 8; nt++) {
                uint32_t b0 = __float_as_uint(Vs[(kc * 8 + tg)     * VSTR + nt * 8 + gr]);
                uint32_t b1 = __float_as_uint(Vs[(kc * 8 + tg + 4) * VSTR + nt * 8 + gr]);
                mma_tf32(of[nt], a0, a1, a2, a3, b0, b1);
            }
        }
    }

    // ---- epilogue: normalize, write [b, t, h*64+d] ----
    float inv_lo = 1.f / Ls[q0w + gr];
    float inv_hi = 1.f / Ls[q0w + gr + 8];
    int b = bh >> 4, h = bh & 15;
    int qg_lo = qb * 128 + q0w + gr;
    int qg_hi = qg_lo + 8;
#pragma unroll
    for (int nt = 0; nt < 8; nt++) {
        int col = nt * 8 + 2 * tg;
        float2 lo = {of[nt][0] * inv_lo, of[nt][1] * inv_lo};
        float2 hi = {of[nt][2] * inv_hi, of[nt][3] * inv_hi};
        *(float2*)(go + (size_t)(b * Tq + qg_lo) * Cq + h * 64 + col) = lo;
        *(float2*)(go + (size_t)(b * Tq + qg_hi) * Cq + h * 64 + col) = hi;
    }
}

// ---------------------------------------------------------------------------
extern "C" void kernel_launch(void* const* d_in, const int* in_sizes, int n_in,
                              void* d_out, int out_size)
{
    const float* x      = (const float*)d_in[0];   // [4,2048,1024]
    const float* w_attn = (const float*)d_in[1];   // [3072,1024]
    const float* w_proj = (const float*)d_in[2];   // [1024,1024]
    float* out = (float*)d_out;                    // [4,2048,1024]

    float *qkv, *q, *k, *v, *o;
    cudaGetSymbolAddress((void**)&qkv, g_qkv);
    cudaGetSymbolAddress((void**)&q,   g_q);
    cudaGetSymbolAddress((void**)&k,   g_k);
    cudaGetSymbolAddress((void**)&v,   g_v);
    cudaGetSymbolAddress((void**)&o,   g_o);

    // 1) qkv = x @ w_attn^T   [8192,3072]
    sgemm_nt<<<dim3(3072 / 128, BT / 128), 256>>>(x, w_attn, qkv, BT, 3 * Cq, Cq);

    // 2) RMSNorm + RoPE + relayout
    norm_rope<<<(Bq * Tq * Hq) / 8, 256>>>(qkv, q, k, v);

    // 3) causal flash attention (tf32 tensor cores)
    cudaFuncSetAttribute(attn_kernel, cudaFuncAttributeMaxDynamicSharedMemorySize,
                         ATTN_SMEM_BYTES);
    attn_kernel<<<dim3(Tq / 128, BHq), 256, ATTN_SMEM_BYTES>>>(q, k, v, o);

    // 4) out = o @ w_proj^T   [8192,1024]
    sgemm_nt<<<dim3(Cq / 128, BT / 128), 256>>>(o, w_proj, out, BT, Cq, Cq);
}

// round 7
// speedup vs baseline: 1.7017x; 1.2606x over previous
#include <cuda_runtime.h>
#include <cuda_bf16.h>
#include <math.h>
#include <stdint.h>

// Problem dims (fixed)
#define Bq  4
#define Tq  2048
#define Cq  1024
#define Hq  16
#define HDq 64
#define BT  8192   // B*T
#define BHq 64     // B*H

// Scratch (device globals — no allocation allowed)
__device__ float g_qkv[BT * 3 * Cq];       // [8192, 3072]
__device__ float g_q[BHq * Tq * HDq];      // [b*H+h, t, d]
__device__ float g_k[BHq * Tq * HDq];
__device__ float g_v[BHq * Tq * HDq];
__device__ float g_o[BT * Cq];             // [8192, 1024] attn output (b,t,h,d)

__device__ __forceinline__ uint32_t f2tf(float f) {
    uint32_t r;
    asm("cvt.rna.tf32.f32 %0, %1;" : "=r"(r) : "f"(f));
    return r;
}
__device__ __forceinline__ float tf_hi(float x) { return __uint_as_float(f2tf(x)); }

__device__ __forceinline__ void mma_tf32(float c[4],
    uint32_t a0, uint32_t a1, uint32_t a2, uint32_t a3,
    uint32_t b0, uint32_t b1)
{
    asm volatile(
        "mma.sync.aligned.m16n8k8.row.col.f32.tf32.tf32.f32 "
        "{%0,%1,%2,%3}, {%4,%5,%6,%7}, {%8,%9}, {%0,%1,%2,%3};"
        : "+f"(c[0]), "+f"(c[1]), "+f"(c[2]), "+f"(c[3])
        : "r"(a0), "r"(a1), "r"(a2), "r"(a3), "r"(b0), "r"(b1));
}

// ---------------------------------------------------------------------------
// 3xTF32 GEMM: C[M,N] = A[M,K] @ B[N,K]^T, fp32-accurate via hi/lo split.
// 128x128 tile, BK=16, 256 threads, 8 warps (2m x 4n), warp tile 64m x 32n.
// ---------------------------------------------------------------------------
#define GS 20
__global__ __launch_bounds__(256) void gemm3x(
    const float* __restrict__ A, const float* __restrict__ B,
    float* __restrict__ C, int M, int N, int K)
{
    __shared__ float Ah[128][GS], Al[128][GS], Bh[128][GS], Bl[128][GS];

    int tid = threadIdx.x;
    int wid = tid >> 5, lane = tid & 31;
    int gr = lane >> 2, tg = lane & 3;
    int wm = (wid & 1) * 64, wn = (wid >> 1) * 32;

    int lrow = tid & 127;
    const float* Gp = (tid < 128)
        ? (A + (size_t)(blockIdx.y * 128 + lrow) * K)
        : (B + (size_t)(blockIdx.x * 128 + lrow) * K);

    float acc[4][4][4];
#pragma unroll
    for (int mf = 0; mf < 4; mf++)
#pragma unroll
        for (int nf = 0; nf < 4; nf++)
#pragma unroll
            for (int j = 0; j < 4; j++) acc[mf][nf][j] = 0.f;

    for (int k0 = 0; k0 < K; k0 += 16) {
        __syncthreads();
        {
            float (*Sh)[GS] = (tid < 128) ? Ah : Bh;
            float (*Sl)[GS] = (tid < 128) ? Al : Bl;
#pragma unroll
            for (int q = 0; q < 4; q++) {
                float4 v = *(const float4*)(Gp + k0 + q * 4);
                float h0 = tf_hi(v.x), h1 = tf_hi(v.y), h2 = tf_hi(v.z), h3 = tf_hi(v.w);
                float l0 = __uint_as_float(f2tf(v.x - h0));
                float l1 = __uint_as_float(f2tf(v.y - h1));
                float l2 = __uint_as_float(f2tf(v.z - h2));
                float l3 = __uint_as_float(f2tf(v.w - h3));
                *(float4*)&Sh[lrow][q * 4] = make_float4(h0, h1, h2, h3);
                *(float4*)&Sl[lrow][q * 4] = make_float4(l0, l1, l2, l3);
            }
        }
        __syncthreads();

#pragma unroll
        for (int kk = 0; kk < 2; kk++) {
            int kb = kk * 8;
            uint32_t bh0[4], bh1[4], bl0[4], bl1[4];
#pragma unroll
            for (int nf = 0; nf < 4; nf++) {
                int col = wn + nf * 8 + gr;
                bh0[nf] = __float_as_uint(Bh[col][kb + tg]);
                bh1[nf] = __float_as_uint(Bh[col][kb + tg + 4]);
                bl0[nf] = __float_as_uint(Bl[col][kb + tg]);
                bl1[nf] = __float_as_uint(Bl[col][kb + tg + 4]);
            }
#pragma unroll
            for (int mf = 0; mf < 4; mf++) {
                int r0 = wm + mf * 16 + gr;
                uint32_t ah0 = __float_as_uint(Ah[r0][kb + tg]);
                uint32_t ah1 = __float_as_uint(Ah[r0 + 8][kb + tg]);
                uint32_t ah2 = __float_as_uint(Ah[r0][kb + tg + 4]);
                uint32_t ah3 = __float_as_uint(Ah[r0 + 8][kb + tg + 4]);
                uint32_t al0 = __float_as_uint(Al[r0][kb + tg]);
                uint32_t al1 = __float_as_uint(Al[r0 + 8][kb + tg]);
                uint32_t al2 = __float_as_uint(Al[r0][kb + tg + 4]);
                uint32_t al3 = __float_as_uint(Al[r0 + 8][kb + tg + 4]);
#pragma unroll
                for (int nf = 0; nf < 4; nf++) {
                    mma_tf32(acc[mf][nf], ah0, ah1, ah2, ah3, bh0[nf], bh1[nf]);
                    mma_tf32(acc[mf][nf], al0, al1, al2, al3, bh0[nf], bh1[nf]);
                    mma_tf32(acc[mf][nf], ah0, ah1, ah2, ah3, bl0[nf], bl1[nf]);
                }
            }
        }
    }

#pragma unroll
    for (int mf = 0; mf < 4; mf++) {
#pragma unroll
        for (int nf = 0; nf < 4; nf++) {
            float* Cp = C + (size_t)(blockIdx.y * 128 + wm + mf * 16 + gr) * N
                          + blockIdx.x * 128 + wn + nf * 8 + 2 * tg;
            *(float2*)Cp = make_float2(acc[mf][nf][0], acc[mf][nf][1]);
            *(float2*)(Cp + (size_t)8 * N) = make_float2(acc[mf][nf][2], acc[mf][nf][3]);
        }
    }
}

// ---------------------------------------------------------------------------
// RMSNorm + RoPE + layout transform.  One warp per (b, t, h).  (unchanged)
// ---------------------------------------------------------------------------
__device__ __forceinline__ float warp_sum(float v) {
    v += __shfl_xor_sync(0xffffffffu, v, 16);
    v += __shfl_xor_sync(0xffffffffu, v, 8);
    v += __shfl_xor_sync(0xffffffffu, v, 4);
    v += __shfl_xor_sync(0xffffffffu, v, 2);
    v += __shfl_xor_sync(0xffffffffu, v, 1);
    return v;
}

__global__ __launch_bounds__(256) void norm_rope(
    const float* __restrict__ qkv,
    float* __restrict__ gq, float* __restrict__ gk, float* __restrict__ gv)
{
    int gw = (blockIdx.x * 256 + threadIdx.x) >> 5;
    int lane = threadIdx.x & 31;
    int h = gw & (Hq - 1);
    int t = (gw >> 4) & (Tq - 1);
    int b = gw >> 15;

    const float* base = qkv + (size_t)(b * Tq + t) * (3 * Cq) + h * HDq;
    float q1 = base[lane],          q2 = base[lane + 32];
    float k1 = base[Cq + lane],     k2 = base[Cq + lane + 32];
    float v1 = base[2 * Cq + lane], v2 = base[2 * Cq + lane + 32];

    float sq = warp_sum(q1 * q1 + q2 * q2);
    float sk = warp_sum(k1 * k1 + k2 * k2);
    const float eps = 1.1920929e-7f;
    float rq = rsqrtf(sq * (1.f / 64.f) + eps);
    float rk = rsqrtf(sk * (1.f / 64.f) + eps);
    q1 *= rq; q2 *= rq; k1 *= rk; k2 *= rk;

    float inv = powf(10000.f, -(float)lane * (1.f / 32.f));
    float fr = (float)t * inv;
    float c = __bfloat162float(__float2bfloat16(cosf(fr)));
    float s = __bfloat162float(__float2bfloat16(sinf(fr)));

    size_t o = ((size_t)(b * Hq + h) * Tq + t) * HDq;
    gq[o + lane]      =  q1 * c + q2 * s;
    gq[o + lane + 32] = -q1 * s + q2 * c;
    gk[o + lane]      =  k1 * c + k2 * s;
    gk[o + lane + 32] = -k1 * s + k2 * c;
    gv[o + lane]      = v1;
    gv[o + lane + 32] = v2;
}

// ---------------------------------------------------------------------------
// Flash attention, tf32 mma, k-dim interleave-permuted smem for v2 frag loads.
// CTA tile 128 q x 64 kv, 256 threads / 8 warps (warp = 16 q rows).
// Permutation: logical l in [0,8) stored at (l<4 ? 2l : 2(l-4)+1), so logical
// pair (tg, tg+4) = physical (2tg, 2tg+1)  -> ld.shared.v2.
// ---------------------------------------------------------------------------
#define QSTR 72
#define ATTN_SMEM_FLOATS (128*QSTR + 64*QSTR + 64*QSTR + 128*QSTR + 3*128)
#define ATTN_SMEM_BYTES  (ATTN_SMEM_FLOATS * 4)

__device__ __forceinline__ uint4 tf4(float4 v) {
    uint4 u;
    u.x = f2tf(v.x); u.y = f2tf(v.y); u.z = f2tf(v.z); u.w = f2tf(v.w);
    return u;
}

__global__ __launch_bounds__(256, 2) void attn_kernel(
    const float* __restrict__ gq, const float* __restrict__ gk,
    const float* __restrict__ gv, float* __restrict__ go)
{
    extern __shared__ float sm[];
    float* Qs = sm;                       // [128][QSTR] perm(d)
    float* Ks = Qs + 128 * QSTR;          // [64][QSTR]  perm(d)
    float* Vs = Ks + 64 * QSTR;           // [64][QSTR]  natural [kv][d]
    float* Ss = Vs + 64 * QSTR;           // [128][QSTR] perm(kv)
    float* Ms = Ss + 128 * QSTR;          // [128]
    float* Ls = Ms + 128;                 // [128]
    float* Cs = Ls + 128;                 // [128]

    int tid = threadIdx.x;
    int wid = tid >> 5;
    int lane = tid & 31;
    int gr = lane >> 2;
    int tg = lane & 3;
    int q0w = wid * 16;

    int qb = (gridDim.x - 1) - blockIdx.x;
    int bh = blockIdx.y;
    const float* qbase = gq + ((size_t)bh * Tq + qb * 128) * 64;
    const float* kbase = gk + (size_t)bh * Tq * 64;
    const float* vbase = gv + (size_t)bh * Tq * 64;

    // Load Q tile: tf32-convert + k-permute
    for (int i = tid; i < 2048; i += 256) {
        int r = i >> 4, c = (i & 15) << 2;
        float4 q4 = *(const float4*)(qbase + (size_t)r * 64 + c);
        float* qp = &Qs[r * QSTR + (c & ~7) + ((c & 4) ? 1 : 0)];
        qp[0] = __uint_as_float(f2tf(q4.x));
        qp[2] = __uint_as_float(f2tf(q4.y));
        qp[4] = __uint_as_float(f2tf(q4.z));
        qp[6] = __uint_as_float(f2tf(q4.w));
    }
    if (tid < 128) { Ms[tid] = -INFINITY; Ls[tid] = 0.f; }

    float of[8][4];
#pragma unroll
    for (int nt = 0; nt < 8; nt++)
#pragma unroll
        for (int j = 0; j < 4; j++) of[nt][j] = 0.f;

    const float scale = 0.125f;
    int nkb = 2 * qb + 2;
    int pc0 = (tg < 2) ? 4 * tg : 4 * tg - 7;   // phys pos of logical col 2tg

    for (int kb = 0; kb < nkb; kb++) {
        __syncthreads();
        for (int i = tid; i < 1024; i += 256) {
            int r = i >> 4, c = (i & 15) << 2;
            float4 k4 = *(const float4*)(kbase + (size_t)(kb * 64 + r) * 64 + c);
            float* kp = &Ks[r * QSTR + (c & ~7) + ((c & 4) ? 1 : 0)];
            kp[0] = __uint_as_float(f2tf(k4.x));
            kp[2] = __uint_as_float(f2tf(k4.y));
            kp[4] = __uint_as_float(f2tf(k4.z));
            kp[6] = __uint_as_float(f2tf(k4.w));
            float4 v4 = *(const float4*)(vbase + (size_t)(kb * 64 + r) * 64 + c);
            *(uint4*)&Vs[r * QSTR + c] = tf4(v4);
        }
        __syncthreads();

        // ---- S = Q @ K^T ----
        float sc[8][4];
#pragma unroll
        for (int nt = 0; nt < 8; nt++)
#pragma unroll
            for (int j = 0; j < 4; j++) sc[nt][j] = 0.f;

#pragma unroll
        for (int kc = 0; kc < 8; kc++) {
            float2 aq0 = *(const float2*)&Qs[(q0w + gr)     * QSTR + kc * 8 + 2 * tg];
            float2 aq1 = *(const float2*)&Qs[(q0w + gr + 8) * QSTR + kc * 8 + 2 * tg];
            uint32_t a0 = __float_as_uint(aq0.x), a2 = __float_as_uint(aq0.y);
            uint32_t a1 = __float_as_uint(aq1.x), a3 = __float_as_uint(aq1.y);
#pragma unroll
            for (int nt = 0; nt < 8; nt++) {
                float2 bk = *(const float2*)&Ks[(nt * 8 + gr) * QSTR + kc * 8 + 2 * tg];
                mma_tf32(sc[nt], a0, a1, a2, a3,
                         __float_as_uint(bk.x), __float_as_uint(bk.y));
            }
        }

        // scale + causal mask (logical cols) + store (physical cols)
        {
            int r0 = q0w + gr;
            bool diag = (kb >= 2 * qb);
            int qg0 = qb * 128 + r0;
            int qg1 = qg0 + 8;
#pragma unroll
            for (int nt = 0; nt < 8; nt++) {
                float lx = sc[nt][0] * scale, ly = sc[nt][1] * scale;
                float hx = sc[nt][2] * scale, hy = sc[nt][3] * scale;
                if (diag) {
                    int kvg = kb * 64 + nt * 8 + 2 * tg;
                    if (kvg     > qg0) lx = -INFINITY;
                    if (kvg + 1 > qg0) ly = -INFINITY;
                    if (kvg     > qg1) hx = -INFINITY;
                    if (kvg + 1 > qg1) hy = -INFINITY;
                }
                Ss[r0 * QSTR + nt * 8 + pc0]           = lx;
                Ss[r0 * QSTR + nt * 8 + pc0 + 2]       = ly;
                Ss[(r0 + 8) * QSTR + nt * 8 + pc0]     = hx;
                Ss[(r0 + 8) * QSTR + nt * 8 + pc0 + 2] = hy;
            }
        }
        __syncthreads();

        // ---- online softmax (2 threads per row; permutation-invariant) ----
        {
            int row = tid >> 1, part = tid & 1;
            float* sr = Ss + row * QSTR + part * 32;
            float mloc = sr[0];
#pragma unroll
            for (int e = 1; e < 32; e++) mloc = fmaxf(mloc, sr[e]);
            mloc = fmaxf(mloc, __shfl_xor_sync(0xffffffffu, mloc, 1));
            float mold = Ms[row];
            float mnew = fmaxf(mold, mloc);
            float suml = 0.f;
#pragma unroll
            for (int e = 0; e < 32; e++) {
                float p = __expf(sr[e] - mnew);
                sr[e] = p;
                suml += p;
            }
            suml += __shfl_xor_sync(0xffffffffu, suml, 1);
            if (part == 0) {
                float corr = __expf(mold - mnew);
                Cs[row] = corr;
                Ls[row] = Ls[row] * corr + suml;
                Ms[row] = mnew;
            }
        }
        __syncthreads();

        // ---- O = O*corr + P @ V ----
        float c_lo = Cs[q0w + gr], c_hi = Cs[q0w + gr + 8];
#pragma unroll
        for (int nt = 0; nt < 8; nt++) {
            of[nt][0] *= c_lo; of[nt][1] *= c_lo;
            of[nt][2] *= c_hi; of[nt][3] *= c_hi;
        }
#pragma unroll
        for (int kc = 0; kc < 8; kc++) {
            float2 p0 = *(const float2*)&Ss[(q0w + gr)     * QSTR + kc * 8 + 2 * tg];
            float2 p1 = *(const float2*)&Ss[(q0w + gr + 8) * QSTR + kc * 8 + 2 * tg];
            uint32_t a0 = f2tf(p0.x), a2 = f2tf(p0.y);
            uint32_t a1 = f2tf(p1.x), a3 = f2tf(p1.y);
#pragma unroll
            for (int nt = 0; nt < 8; nt++) {
                uint32_t b0 = __float_as_uint(Vs[(kc * 8 + tg)     * QSTR + nt * 8 + gr]);
                uint32_t b1 = __float_as_uint(Vs[(kc * 8 + tg + 4) * QSTR + nt * 8 + gr]);
                mma_tf32(of[nt], a0, a1, a2, a3, b0, b1);
            }
        }
    }

    // ---- epilogue ----
    float inv_lo = 1.f / Ls[q0w + gr];
    float inv_hi = 1.f / Ls[q0w + gr + 8];
    int b = bh >> 4, h = bh & 15;
    int qg_lo = qb * 128 + q0w + gr;
    int qg_hi = qg_lo + 8;
#pragma unroll
    for (int nt = 0; nt < 8; nt++) {
        int col = nt * 8 + 2 * tg;
        float2 lo = {of[nt][0] * inv_lo, of[nt][1] * inv_lo};
        float2 hi = {of[nt][2] * inv_hi, of[nt][3] * inv_hi};
        *(float2*)(go + (size_t)(b * Tq + qg_lo) * Cq + h * 64 + col) = lo;
        *(float2*)(go + (size_t)(b * Tq + qg_hi) * Cq + h * 64 + col) = hi;
    }
}

// ---------------------------------------------------------------------------
extern "C" void kernel_launch(void* const* d_in, const int* in_sizes, int n_in,
                              void* d_out, int out_size)
{
    const float* x      = (const float*)d_in[0];   // [4,2048,1024]
    const float* w_attn = (const float*)d_in[1];   // [3072,1024]
    const float* w_proj = (const float*)d_in[2];   // [1024,1024]
    float* out = (float*)d_out;                    // [4,2048,1024]

    float *qkv, *q, *k, *v, *o;
    cudaGetSymbolAddress((void**)&qkv, g_qkv);
    cudaGetSymbolAddress((void**)&q,   g_q);
    cudaGetSymbolAddress((void**)&k,   g_k);
    cudaGetSymbolAddress((void**)&v,   g_v);
    cudaGetSymbolAddress((void**)&o,   g_o);

    // 1) qkv = x @ w_attn^T   [8192,3072]
    gemm3x<<<dim3(3072 / 128, BT / 128), 256>>>(x, w_attn, qkv, BT, 3 * Cq, Cq);

    // 2) RMSNorm + RoPE + relayout
    norm_rope<<<(Bq * Tq * Hq) / 8, 256>>>(qkv, q, k, v);

    // 3) causal flash attention (tf32 tensor cores)
    cudaFuncSetAttribute(attn_kernel, cudaFuncAttributeMaxDynamicSharedMemorySize,
                         ATTN_SMEM_BYTES);
    attn_kernel<<<dim3(Tq / 128, BHq), 256, ATTN_SMEM_BYTES>>>(q, k, v, o);

    // 4) out = o @ w_proj^T   [8192,1024]
    gemm3x<<<dim3(Cq / 128, BT / 128), 256>>>(o, w_proj, out, BT, Cq, Cq);
}